// round 5
// baseline (speedup 1.0000x reference)
#include <cuda_runtime.h>
#include <math.h>
#include <stdint.h>

#define C_IN   256
#define HGT    200
#define WID    200
#define HWNUM  40000
#define NA     9
#define KTOT   2304
#define NSCORE 360000
#define PRE    6000
#define POST   1000
#define IMGSZ  1600.0f
#define NMS_THR 0.7f
#define MINSZ  1.0f
#define BCLIP  4.135166556742356f   /* log(1000/16) */
#define MASKW  94                   /* ceil(6000/64) */

/* ------------------------- scratch (device globals) ------------------------ */
__device__ float              g_t[C_IN * HWNUM];          /* conv output (relu'd) */
__device__ unsigned int       g_keys[NSCORE];             /* monotone score keys  */
__device__ float              g_deltas[NSCORE * 4];
__device__ int                g_hist1[65536];
__device__ int                g_hist2[65536];
__device__ int                g_selHigh;
__device__ int                g_cntAbove1;
__device__ unsigned int       g_T;
__device__ int                g_nAbove;
__device__ int                g_cntHigh;
__device__ int                g_cntEq;
__device__ unsigned int       g_tieIdx[8192];
__device__ unsigned long long g_list[8192];               /* (key<<32)|(~idx)     */
__device__ float              g_boxes[PRE * 4];
__device__ int                g_valid[PRE];
__device__ unsigned long long g_mask[(size_t)PRE * MASKW];

/* --------------------------------- zero ----------------------------------- */
__global__ void zero_kernel() {
    int i = blockIdx.x * blockDim.x + threadIdx.x;
    if (i < 65536) { g_hist1[i] = 0; g_hist2[i] = 0; }
    if (i == 0) { g_cntHigh = 0; g_cntEq = 0; }
}

/* ---- 3x3 conv (implicit GEMM, sequential FMA over k' = (r,s,ci) order) ---- */
/* XLA-CPU canonicalizes NCHW/OIHW to NHWC/HWIO, so Eigen accumulates the      */
/* contraction sequentially over k' = (r*3+s)*256 + ci. We reproduce exactly   */
/* that order: one accumulator per output, k' stepped 0..2303 ascending.       */
/* Within an 8-wide k-tile, (r,s) is fixed and ci spans 8 consecutive planes.  */
__global__ __launch_bounds__(256, 2)
void conv3x3_kernel(const float* __restrict__ x, const float* __restrict__ w,
                    const float* __restrict__ bias) {
    __shared__ float As[2][8][128];
    __shared__ float Bs[2][8][128];
    const int tid = threadIdx.x;
    const int m0 = blockIdx.y * 128;
    const int p0 = blockIdx.x * 128;
    const int a_m = tid >> 1;          /* 0..127 : out channel within tile */
    const int a_k = (tid & 1) * 4;     /* 0 or 4 : k-subrow               */
    const int b_kr = tid >> 5;         /* 0..7   : k-row                  */
    const int b_pc = (tid & 31) * 4;   /* 0..124 : pixel col              */
    const int tx = tid & 15, ty = tid >> 4;

    float aReg[4] = {0.f, 0.f, 0.f, 0.f};
    float4 bReg = make_float4(0.f, 0.f, 0.f, 0.f);

    /* tile index it: rs = it>>5 (0..8), ci0 = (it&31)*8 */
    auto loadTiles = [&](int it) {
        int rs = it >> 5;
        int ci0 = (it & 31) * 8;
        int r = rs / 3 - 1;
        int s = rs - (rs / 3) * 3 - 1;
        /* A: w[m][ci][r][s] at k' rows ci0+a_k .. ci0+a_k+3, stride 9 gather */
        const float* wrow = w + (size_t)(m0 + a_m) * KTOT + (size_t)(ci0 + a_k) * 9 + rs;
#pragma unroll
        for (int j = 0; j < 4; j++) aReg[j] = wrow[j * 9];
        /* B: x[ci0+b_kr][h+r][w+s] for 4 consecutive pixels */
        const float* base = x + (size_t)(ci0 + b_kr) * HWNUM;
        float bv[4];
#pragma unroll
        for (int jj = 0; jj < 4; jj++) {
            int p = p0 + b_pc + jj;
            float v = 0.f;
            if (p < HWNUM) {
                int h = p / 200;
                int wc = p - h * 200;
                int hh = h + r, wcc = wc + s;
                if (hh >= 0 && hh < HGT && wcc >= 0 && wcc < WID)
                    v = base[hh * WID + wcc];
            }
            bv[jj] = v;
        }
        bReg = make_float4(bv[0], bv[1], bv[2], bv[3]);
    };
    auto storeTiles = [&](int buf) {
        As[buf][a_k + 0][a_m] = aReg[0];
        As[buf][a_k + 1][a_m] = aReg[1];
        As[buf][a_k + 2][a_m] = aReg[2];
        As[buf][a_k + 3][a_m] = aReg[3];
        *reinterpret_cast<float4*>(&Bs[buf][b_kr][b_pc]) = bReg;
    };

    float acc[8][8];
#pragma unroll
    for (int i = 0; i < 8; i++)
#pragma unroll
        for (int j = 0; j < 8; j++) acc[i][j] = 0.f;

    loadTiles(0);
    storeTiles(0);
    __syncthreads();
    int cur = 0;
    const int NIT = KTOT / 8;  /* 288 */
    for (int it = 0; it < NIT; it++) {
        if (it + 1 < NIT) loadTiles(it + 1);
#pragma unroll
        for (int kk = 0; kk < 8; kk++) {
            float4 a0 = *reinterpret_cast<const float4*>(&As[cur][kk][ty * 8]);
            float4 a1 = *reinterpret_cast<const float4*>(&As[cur][kk][ty * 8 + 4]);
            float4 b0 = *reinterpret_cast<const float4*>(&Bs[cur][kk][tx * 8]);
            float4 b1 = *reinterpret_cast<const float4*>(&Bs[cur][kk][tx * 8 + 4]);
            float av[8] = {a0.x, a0.y, a0.z, a0.w, a1.x, a1.y, a1.z, a1.w};
            float bv[8] = {b0.x, b0.y, b0.z, b0.w, b1.x, b1.y, b1.z, b1.w};
#pragma unroll
            for (int i = 0; i < 8; i++)
#pragma unroll
                for (int j = 0; j < 8; j++)
                    acc[i][j] = fmaf(av[i], bv[j], acc[i][j]);
        }
        if (it + 1 < NIT) {
            storeTiles(cur ^ 1);
            __syncthreads();
            cur ^= 1;
        }
    }
#pragma unroll
    for (int i = 0; i < 8; i++) {
        int m = m0 + ty * 8 + i;
        float bv = bias[m];
#pragma unroll
        for (int j = 0; j < 8; j++) {
            int p = p0 + tx * 8 + j;
            if (p < HWNUM)
                g_t[(size_t)m * HWNUM + p] = fmaxf(__fadd_rn(acc[i][j], bv), 0.f);
        }
    }
}

/* ------- 1x1 heads (plain sequential FMA): obj -> keys, reg -> deltas ------ */
__global__ __launch_bounds__(256)
void heads_kernel(const float* __restrict__ wObj, const float* __restrict__ bObj,
                  const float* __restrict__ wReg, const float* __restrict__ bReg) {
    __shared__ float ws[45 * 256];
    __shared__ float bs[45];
    int tid = threadIdx.x;
    for (int i = tid; i < 9 * 256; i += 256) ws[i] = wObj[i];
    for (int i = tid; i < 36 * 256; i += 256) ws[9 * 256 + i] = wReg[i];
    if (tid < 9) bs[tid] = bObj[tid];
    if (tid < 36) bs[9 + tid] = bReg[tid];
    __syncthreads();

    int p = blockIdx.x * 256 + tid;
    if (p >= HWNUM) return;
    float acc[45];
#pragma unroll
    for (int o = 0; o < 45; o++) acc[o] = 0.f;
    for (int ci = 0; ci < 256; ci++) {
        float a = g_t[(size_t)ci * HWNUM + p];
#pragma unroll
        for (int o = 0; o < 45; o++)
            acc[o] = fmaf(a, ws[o * 256 + ci], acc[o]);
    }
#pragma unroll
    for (int a = 0; a < 9; a++) {
        float s = __fadd_rn(acc[a], bs[a]);
        unsigned u = __float_as_uint(s);
        g_keys[p * 9 + a] = (u & 0x80000000u) ? ~u : (u | 0x80000000u);
    }
#pragma unroll
    for (int c = 0; c < 36; c++)
        g_deltas[(size_t)p * 36 + c] = __fadd_rn(acc[9 + c], bs[9 + c]);
}

/* ------------------------------ radix select ------------------------------- */
__global__ void hist1_kernel() {
    int i = blockIdx.x * blockDim.x + threadIdx.x;
    if (i < NSCORE) atomicAdd(&g_hist1[g_keys[i] >> 16], 1);
}

__global__ void select_kernel(int pass) {
    const int* hist = (pass == 0) ? g_hist1 : g_hist2;
    __shared__ int csum[1024];
    __shared__ int sbase;
    int t = threadIdx.x;
    if (t == 0) sbase = (pass == 0) ? 0 : g_cntAbove1;
    __syncthreads();
    int base = sbase;
    int s = 0;
    int start = t * 64;
    for (int k = 0; k < 64; k++) s += hist[65535 - (start + k)];
    csum[t] = s;
    __syncthreads();
    for (int off = 1; off < 1024; off <<= 1) {
        int v = (t >= off) ? csum[t - off] : 0;
        __syncthreads();
        csum[t] += v;
        __syncthreads();
    }
    int incl = csum[t];
    int excl = incl - s;
    if (base + excl < PRE && base + incl >= PRE) {
        int acc = base + excl;
        for (int k = 0; k < 64; k++) {
            int b = 65535 - (start + k);
            int c = hist[b];
            if (acc + c >= PRE) {
                if (pass == 0) { g_selHigh = b; g_cntAbove1 = acc; }
                else { g_T = (((unsigned)g_selHigh) << 16) | (unsigned)b; g_nAbove = acc; }
                break;
            }
            acc += c;
        }
    }
}

__global__ void hist2_kernel() {
    int i = blockIdx.x * blockDim.x + threadIdx.x;
    if (i < NSCORE) {
        unsigned k = g_keys[i];
        if ((int)(k >> 16) == g_selHigh) atomicAdd(&g_hist2[k & 0xFFFFu], 1);
    }
}

__global__ void compact_kernel() {
    int i = blockIdx.x * blockDim.x + threadIdx.x;
    if (i >= NSCORE) return;
    unsigned k = g_keys[i];
    unsigned T = g_T;
    if (k > T) {
        int pos = atomicAdd(&g_cntHigh, 1);
        g_list[pos] = (((unsigned long long)k) << 32) |
                      (unsigned long long)(0xFFFFFFFFu - (unsigned)i);
    } else if (k == T) {
        int pos = atomicAdd(&g_cntEq, 1);
        if (pos < 8192) g_tieIdx[pos] = (unsigned)i;
    }
}

/* sort tie indices ascending, append needed count, pad list */
__global__ void finalize_kernel() {
    __shared__ unsigned sIdx[8192];
    int t = threadIdx.x;
    int cnt = g_cntEq; if (cnt > 8192) cnt = 8192;
    int need = PRE - g_nAbove;
    for (int i = t; i < 8192; i += 1024) sIdx[i] = (i < cnt) ? g_tieIdx[i] : 0xFFFFFFFFu;
    __syncthreads();
    for (int k = 2; k <= 8192; k <<= 1)
        for (int j = k >> 1; j > 0; j >>= 1) {
            for (int i = t; i < 8192; i += 1024) {
                int l = i ^ j;
                if (l > i) {
                    unsigned a = sIdx[i], b = sIdx[l];
                    bool up = ((i & k) == 0);
                    if ((a > b) == up) { sIdx[i] = b; sIdx[l] = a; }
                }
            }
            __syncthreads();
        }
    unsigned T = g_T;
    int nA = g_nAbove;
    for (int j = t; j < need; j += 1024)
        g_list[nA + j] = (((unsigned long long)T) << 32) |
                         (unsigned long long)(0xFFFFFFFFu - sIdx[j]);
    for (int j = PRE + t; j < 8192; j += 1024) g_list[j] = 0ull;
}

/* descending bitonic sort of the 8192 composites (zeros sink to the end) */
__global__ void sort_kernel() {
    extern __shared__ unsigned long long sm[];
    int t = threadIdx.x;
    for (int i = t; i < 8192; i += 1024) sm[i] = g_list[i];
    __syncthreads();
    for (int k = 2; k <= 8192; k <<= 1)
        for (int j = k >> 1; j > 0; j >>= 1) {
            for (int i = t; i < 8192; i += 1024) {
                int l = i ^ j;
                if (l > i) {
                    unsigned long long a = sm[i], b = sm[l];
                    bool up = ((i & k) == 0);
                    if ((a < b) == up) { sm[i] = b; sm[l] = a; }
                }
            }
            __syncthreads();
        }
    for (int i = t; i < 8192; i += 1024) g_list[i] = sm[i];
}

/* ---------------- decode/clip — exact fp32, UNFUSED (match XLA) ------------ */
__global__ void decode_kernel(const float* __restrict__ anchors) {
    int j = blockIdx.x * blockDim.x + threadIdx.x;
    if (j >= PRE) return;
    unsigned long long comp = g_list[j];
    unsigned idx = 0xFFFFFFFFu - (unsigned)(comp & 0xFFFFFFFFull);
    float4 an = reinterpret_cast<const float4*>(anchors)[idx];
    float4 dl = reinterpret_cast<const float4*>(g_deltas)[idx];
    float wa = __fsub_rn(an.z, an.x);
    float ha = __fsub_rn(an.w, an.y);
    float xa = __fadd_rn(an.x, __fmul_rn(0.5f, wa));
    float ya = __fadd_rn(an.y, __fmul_rn(0.5f, ha));
    float dw = fminf(dl.z, BCLIP), dh = fminf(dl.w, BCLIP);
    float cx = __fadd_rn(__fmul_rn(dl.x, wa), xa);
    float cy = __fadd_rn(__fmul_rn(dl.y, ha), ya);
    float ew = (float)exp((double)dw);   /* exactly-rounded fp32 exp */
    float eh = (float)exp((double)dh);
    float wb = __fmul_rn(ew, wa);
    float hb = __fmul_rn(eh, ha);
    float x1 = __fsub_rn(cx, __fmul_rn(0.5f, wb));
    float y1 = __fsub_rn(cy, __fmul_rn(0.5f, hb));
    float x2 = __fadd_rn(cx, __fmul_rn(0.5f, wb));
    float y2 = __fadd_rn(cy, __fmul_rn(0.5f, hb));
    x1 = fminf(fmaxf(x1, 0.f), IMGSZ);
    y1 = fminf(fmaxf(y1, 0.f), IMGSZ);
    x2 = fminf(fmaxf(x2, 0.f), IMGSZ);
    y2 = fminf(fmaxf(y2, 0.f), IMGSZ);
    reinterpret_cast<float4*>(g_boxes)[j] = make_float4(x1, y1, x2, y2);
    g_valid[j] = (__fsub_rn(x2, x1) >= MINSZ) && (__fsub_rn(y2, y1) >= MINSZ);
}

/* ----------- NMS suppression mask — exact fp32, UNFUSED (match XLA) -------- */
__global__ void nms_mask_kernel() {
    int rb = blockIdx.y, cb = blockIdx.x;
    int t = threadIdx.x;
    __shared__ float4 cbox[64];
    int j0 = cb * 64;
    int jg = j0 + t;
    cbox[t] = (jg < PRE) ? reinterpret_cast<const float4*>(g_boxes)[jg]
                         : make_float4(0.f, 0.f, 0.f, 0.f);
    __syncthreads();
    int i = rb * 64 + t;
    if (i >= PRE) return;
    unsigned long long bits = 0ull;
    if (j0 + 63 > i) {
        float4 b = reinterpret_cast<const float4*>(g_boxes)[i];
        float a1 = __fmul_rn(__fsub_rn(b.z, b.x), __fsub_rn(b.w, b.y));
        int jmax = min(64, PRE - j0);
        for (int jj = 0; jj < jmax; jj++) {
            int j = j0 + jj;
            if (j <= i) continue;
            float4 c = cbox[jj];
            float lx = fmaxf(b.x, c.x), ly = fmaxf(b.y, c.y);
            float rx = fminf(b.z, c.z), ry = fminf(b.w, c.w);
            float iw = fmaxf(__fsub_rn(rx, lx), 0.f);
            float ih = fmaxf(__fsub_rn(ry, ly), 0.f);
            float inter = __fmul_rn(iw, ih);
            float a2 = __fmul_rn(__fsub_rn(c.z, c.x), __fsub_rn(c.w, c.y));
            float den = fmaxf(__fsub_rn(__fadd_rn(a1, a2), inter), 1e-6f);
            float iou = __fdiv_rn(inter, den);
            if (iou > NMS_THR) bits |= (1ull << jj);
        }
    }
    g_mask[(size_t)i * MASKW + cb] = bits;
}

/* ------------------- sequential greedy scan (single warp) ------------------ */
__global__ void nms_scan_kernel(float* __restrict__ out) {
    __shared__ volatile unsigned long long rem[MASKW];
    int lane = threadIdx.x;  /* 32 threads */
    for (int i = lane; i < POST * 4; i += 32) out[i] = 0.f;
    for (int w = lane; w < MASKW; w += 32) {
        unsigned long long m = 0ull;
        int base = w * 64;
        for (int k = 0; k < 64; k++) {
            int j = base + k;
            if (j >= PRE || !g_valid[j]) m |= (1ull << k);
        }
        rem[w] = m;
    }
    __syncwarp();
    int nkept = 0;
    for (int i = 0; i < PRE && nkept < POST; i++) {
        bool r = (rem[i >> 6] >> (i & 63)) & 1ull;
        if (!r) {
            if (lane < 4) out[nkept * 4 + lane] = g_boxes[i * 4 + lane];
            nkept++;
            const unsigned long long* row = &g_mask[(size_t)i * MASKW];
            for (int w = lane; w < MASKW; w += 32) rem[w] = rem[w] | row[w];
            __syncwarp();
        }
    }
}

/* --------------------------------- launch ---------------------------------- */
extern "C" void kernel_launch(void* const* d_in, const int* in_sizes, int n_in,
                              void* d_out, int out_size) {
    (void)in_sizes; (void)n_in; (void)out_size;
    const float* feature = (const float*)d_in[0];
    const float* anchors = (const float*)d_in[1];
    const float* w_conv  = (const float*)d_in[2];
    const float* b_conv  = (const float*)d_in[3];
    const float* w_obj   = (const float*)d_in[4];
    const float* b_obj   = (const float*)d_in[5];
    const float* w_reg   = (const float*)d_in[6];
    const float* b_reg   = (const float*)d_in[7];
    float* out = (float*)d_out;

    cudaFuncSetAttribute(sort_kernel, cudaFuncAttributeMaxDynamicSharedMemorySize, 65536);

    zero_kernel<<<256, 256>>>();
    conv3x3_kernel<<<dim3(313, 2), 256>>>(feature, w_conv, b_conv);
    heads_kernel<<<157, 256>>>(w_obj, b_obj, w_reg, b_reg);
    hist1_kernel<<<1407, 256>>>();
    select_kernel<<<1, 1024>>>(0);
    hist2_kernel<<<1407, 256>>>();
    select_kernel<<<1, 1024>>>(1);
    compact_kernel<<<1407, 256>>>();
    finalize_kernel<<<1, 1024>>>();
    sort_kernel<<<1, 1024, 65536>>>();
    decode_kernel<<<24, 256>>>(anchors);
    nms_mask_kernel<<<dim3(94, 94), 64>>>();
    nms_scan_kernel<<<1, 32>>>(out);
}

// round 6
// speedup vs baseline: 1.3351x; 1.3351x over previous
#include <cuda_runtime.h>
#include <math.h>
#include <stdint.h>

#define C_IN   256
#define HGT    200
#define WID    200
#define HWNUM  40000
#define NA     9
#define KTOT   2304
#define NSCORE 360000
#define PRE    6000
#define POST   1000
#define IMGSZ  1600.0f
#define NMS_THR 0.7f
#define MINSZ  1.0f
#define BCLIP  4.135166556742356f   /* log(1000/16) */
#define MASKW  94                   /* ceil(6000/64) */

/* ------------------------- scratch (device globals) ------------------------ */
__device__ float              g_wT[KTOT * 256];           /* w transposed: [k'][m] */
__device__ float              g_t[C_IN * HWNUM];          /* conv output (relu'd) */
__device__ unsigned int       g_keys[NSCORE];             /* monotone score keys  */
__device__ float              g_deltas[NSCORE * 4];
__device__ int                g_hist1[65536];
__device__ int                g_hist2[65536];
__device__ int                g_selHigh;
__device__ int                g_cntAbove1;
__device__ unsigned int       g_T;
__device__ int                g_nAbove;
__device__ int                g_cntHigh;
__device__ int                g_cntEq;
__device__ unsigned int       g_tieIdx[8192];
__device__ unsigned long long g_list[8192];               /* (key<<32)|(~idx)     */
__device__ float              g_boxes[PRE * 4];
__device__ int                g_valid[PRE];
__device__ unsigned long long g_mask[(size_t)PRE * MASKW];

/* --------------------------------- zero ----------------------------------- */
__global__ void zero_kernel() {
    int i = blockIdx.x * blockDim.x + threadIdx.x;
    if (i < 65536) { g_hist1[i] = 0; g_hist2[i] = 0; }
    if (i == 0) { g_cntHigh = 0; g_cntEq = 0; }
}

/* ------------- one-time weight transpose: wT[k'][m], k'=(rs,ci) ------------ */
__global__ void transpose_w_kernel(const float* __restrict__ w) {
    int idx = blockIdx.x * blockDim.x + threadIdx.x;   /* write-coalesced in m */
    if (idx >= KTOT * 256) return;
    int kp = idx >> 8;          /* k' = rs*256 + ci */
    int m  = idx & 255;
    int ci = kp & 255;
    int rs = kp >> 8;
    g_wT[idx] = w[(size_t)m * KTOT + ci * 9 + rs];
}

/* ---- 3x3 conv (implicit GEMM, sequential FMA over k' = (r,s,ci) order) ---- */
/* Bit-exact anchor: one accumulator per output, k' stepped 0..2303 ascending. */
/* A now loaded coalesced from the transposed weights.                         */
__global__ __launch_bounds__(256, 2)
void conv3x3_kernel(const float* __restrict__ x, const float* __restrict__ bias) {
    __shared__ float As[2][8][128];
    __shared__ float Bs[2][8][128];
    const int tid = threadIdx.x;
    const int m0 = blockIdx.y * 128;
    const int p0 = blockIdx.x * 128;
    const int kr = tid >> 5;           /* 0..7   : k-row within tile   */
    const int lc = (tid & 31) * 4;     /* 0..124 : column (m or p)     */
    const int tx = tid & 15, ty = tid >> 4;

    float4 aReg = make_float4(0.f, 0.f, 0.f, 0.f);
    float4 bReg = make_float4(0.f, 0.f, 0.f, 0.f);

    /* tile index it: k0 = it*8; rs = k0>>8 constant within tile (256|8) */
    auto loadTiles = [&](int it) {
        int k0 = it * 8;
        aReg = *reinterpret_cast<const float4*>(&g_wT[(size_t)(k0 + kr) * 256 + m0 + lc]);
        int kp = k0 + kr;
        int rs = kp >> 8;
        int ci = kp & 255;
        int r = rs / 3 - 1;
        int s = rs - (rs / 3) * 3 - 1;
        const float* base = x + (size_t)ci * HWNUM;
        float bv[4];
#pragma unroll
        for (int jj = 0; jj < 4; jj++) {
            int p = p0 + lc + jj;
            float v = 0.f;
            if (p < HWNUM) {
                int h = p / 200;
                int wc = p - h * 200;
                int hh = h + r, wcc = wc + s;
                if (hh >= 0 && hh < HGT && wcc >= 0 && wcc < WID)
                    v = base[hh * WID + wcc];
            }
            bv[jj] = v;
        }
        bReg = make_float4(bv[0], bv[1], bv[2], bv[3]);
    };
    auto storeTiles = [&](int buf) {
        *reinterpret_cast<float4*>(&As[buf][kr][lc]) = aReg;
        *reinterpret_cast<float4*>(&Bs[buf][kr][lc]) = bReg;
    };

    float acc[8][8];
#pragma unroll
    for (int i = 0; i < 8; i++)
#pragma unroll
        for (int j = 0; j < 8; j++) acc[i][j] = 0.f;

    loadTiles(0);
    storeTiles(0);
    __syncthreads();
    int cur = 0;
    const int NIT = KTOT / 8;  /* 288 */
    for (int it = 0; it < NIT; it++) {
        if (it + 1 < NIT) loadTiles(it + 1);
#pragma unroll
        for (int kk = 0; kk < 8; kk++) {
            float4 a0 = *reinterpret_cast<const float4*>(&As[cur][kk][ty * 8]);
            float4 a1 = *reinterpret_cast<const float4*>(&As[cur][kk][ty * 8 + 4]);
            float4 b0 = *reinterpret_cast<const float4*>(&Bs[cur][kk][tx * 8]);
            float4 b1 = *reinterpret_cast<const float4*>(&Bs[cur][kk][tx * 8 + 4]);
            float av[8] = {a0.x, a0.y, a0.z, a0.w, a1.x, a1.y, a1.z, a1.w};
            float bv[8] = {b0.x, b0.y, b0.z, b0.w, b1.x, b1.y, b1.z, b1.w};
#pragma unroll
            for (int i = 0; i < 8; i++)
#pragma unroll
                for (int j = 0; j < 8; j++)
                    acc[i][j] = fmaf(av[i], bv[j], acc[i][j]);
        }
        if (it + 1 < NIT) {
            storeTiles(cur ^ 1);
            __syncthreads();
            cur ^= 1;
        }
    }
#pragma unroll
    for (int i = 0; i < 8; i++) {
        int m = m0 + ty * 8 + i;
        float bv = bias[m];
#pragma unroll
        for (int j = 0; j < 8; j++) {
            int p = p0 + tx * 8 + j;
            if (p < HWNUM)
                g_t[(size_t)m * HWNUM + p] = fmaxf(__fadd_rn(acc[i][j], bv), 0.f);
        }
    }
}

/* --- 1x1 heads (plain sequential FMA) + fused hist1 of the score keys ------ */
__global__ __launch_bounds__(256)
void heads_kernel(const float* __restrict__ wObj, const float* __restrict__ bObj,
                  const float* __restrict__ wReg, const float* __restrict__ bReg) {
    __shared__ float ws[45 * 256];
    __shared__ float bs[45];
    int tid = threadIdx.x;
    for (int i = tid; i < 9 * 256; i += 256) ws[i] = wObj[i];
    for (int i = tid; i < 36 * 256; i += 256) ws[9 * 256 + i] = wReg[i];
    if (tid < 9) bs[tid] = bObj[tid];
    if (tid < 36) bs[9 + tid] = bReg[tid];
    __syncthreads();

    int p = blockIdx.x * 256 + tid;
    if (p >= HWNUM) return;
    float acc[45];
#pragma unroll
    for (int o = 0; o < 45; o++) acc[o] = 0.f;
    for (int ci = 0; ci < 256; ci++) {
        float a = g_t[(size_t)ci * HWNUM + p];
#pragma unroll
        for (int o = 0; o < 45; o++)
            acc[o] = fmaf(a, ws[o * 256 + ci], acc[o]);
    }
#pragma unroll
    for (int a = 0; a < 9; a++) {
        float s = __fadd_rn(acc[a], bs[a]);
        unsigned u = __float_as_uint(s);
        unsigned key = (u & 0x80000000u) ? ~u : (u | 0x80000000u);
        g_keys[p * 9 + a] = key;
        atomicAdd(&g_hist1[key >> 16], 1);
    }
#pragma unroll
    for (int c = 0; c < 36; c++)
        g_deltas[(size_t)p * 36 + c] = __fadd_rn(acc[9 + c], bs[9 + c]);
}

/* ------------------------------ radix select ------------------------------- */
__global__ void select_kernel(int pass) {
    const int* hist = (pass == 0) ? g_hist1 : g_hist2;
    __shared__ int csum[1024];
    __shared__ int sbase;
    int t = threadIdx.x;
    if (t == 0) sbase = (pass == 0) ? 0 : g_cntAbove1;
    __syncthreads();
    int base = sbase;
    int s = 0;
    int start = t * 64;
    for (int k = 0; k < 64; k++) s += hist[65535 - (start + k)];
    csum[t] = s;
    __syncthreads();
    for (int off = 1; off < 1024; off <<= 1) {
        int v = (t >= off) ? csum[t - off] : 0;
        __syncthreads();
        csum[t] += v;
        __syncthreads();
    }
    int incl = csum[t];
    int excl = incl - s;
    if (base + excl < PRE && base + incl >= PRE) {
        int acc = base + excl;
        for (int k = 0; k < 64; k++) {
            int b = 65535 - (start + k);
            int c = hist[b];
            if (acc + c >= PRE) {
                if (pass == 0) { g_selHigh = b; g_cntAbove1 = acc; }
                else { g_T = (((unsigned)g_selHigh) << 16) | (unsigned)b; g_nAbove = acc; }
                break;
            }
            acc += c;
        }
    }
}

__global__ void hist2_kernel() {
    int i = blockIdx.x * blockDim.x + threadIdx.x;
    if (i < NSCORE) {
        unsigned k = g_keys[i];
        if ((int)(k >> 16) == g_selHigh) atomicAdd(&g_hist2[k & 0xFFFFu], 1);
    }
}

__global__ void compact_kernel() {
    int i = blockIdx.x * blockDim.x + threadIdx.x;
    if (i >= NSCORE) return;
    unsigned k = g_keys[i];
    unsigned T = g_T;
    if (k > T) {
        int pos = atomicAdd(&g_cntHigh, 1);
        g_list[pos] = (((unsigned long long)k) << 32) |
                      (unsigned long long)(0xFFFFFFFFu - (unsigned)i);
    } else if (k == T) {
        int pos = atomicAdd(&g_cntEq, 1);
        if (pos < 8192) g_tieIdx[pos] = (unsigned)i;
    }
}

/* sort tie indices ascending, append needed count, pad list */
__global__ void finalize_kernel() {
    __shared__ unsigned sIdx[8192];
    int t = threadIdx.x;
    int cnt = g_cntEq; if (cnt > 8192) cnt = 8192;
    int need = PRE - g_nAbove;
    for (int i = t; i < 8192; i += 1024) sIdx[i] = (i < cnt) ? g_tieIdx[i] : 0xFFFFFFFFu;
    __syncthreads();
    for (int k = 2; k <= 8192; k <<= 1)
        for (int j = k >> 1; j > 0; j >>= 1) {
            for (int i = t; i < 8192; i += 1024) {
                int l = i ^ j;
                if (l > i) {
                    unsigned a = sIdx[i], b = sIdx[l];
                    bool up = ((i & k) == 0);
                    if ((a > b) == up) { sIdx[i] = b; sIdx[l] = a; }
                }
            }
            __syncthreads();
        }
    unsigned T = g_T;
    int nA = g_nAbove;
    for (int j = t; j < need; j += 1024)
        g_list[nA + j] = (((unsigned long long)T) << 32) |
                         (unsigned long long)(0xFFFFFFFFu - sIdx[j]);
    for (int j = PRE + t; j < 8192; j += 1024) g_list[j] = 0ull;
}

/* descending bitonic sort of the 8192 composites (zeros sink to the end) */
__global__ void sort_kernel() {
    extern __shared__ unsigned long long sm[];
    int t = threadIdx.x;
    for (int i = t; i < 8192; i += 1024) sm[i] = g_list[i];
    __syncthreads();
    for (int k = 2; k <= 8192; k <<= 1)
        for (int j = k >> 1; j > 0; j >>= 1) {
            for (int i = t; i < 8192; i += 1024) {
                int l = i ^ j;
                if (l > i) {
                    unsigned long long a = sm[i], b = sm[l];
                    bool up = ((i & k) == 0);
                    if ((a < b) == up) { sm[i] = b; sm[l] = a; }
                }
            }
            __syncthreads();
        }
    for (int i = t; i < 8192; i += 1024) g_list[i] = sm[i];
}

/* ---------------- decode/clip — exact fp32, UNFUSED (match XLA) ------------ */
__global__ void decode_kernel(const float* __restrict__ anchors) {
    int j = blockIdx.x * blockDim.x + threadIdx.x;
    if (j >= PRE) return;
    unsigned long long comp = g_list[j];
    unsigned idx = 0xFFFFFFFFu - (unsigned)(comp & 0xFFFFFFFFull);
    float4 an = reinterpret_cast<const float4*>(anchors)[idx];
    float4 dl = reinterpret_cast<const float4*>(g_deltas)[idx];
    float wa = __fsub_rn(an.z, an.x);
    float ha = __fsub_rn(an.w, an.y);
    float xa = __fadd_rn(an.x, __fmul_rn(0.5f, wa));
    float ya = __fadd_rn(an.y, __fmul_rn(0.5f, ha));
    float dw = fminf(dl.z, BCLIP), dh = fminf(dl.w, BCLIP);
    float cx = __fadd_rn(__fmul_rn(dl.x, wa), xa);
    float cy = __fadd_rn(__fmul_rn(dl.y, ha), ya);
    float ew = (float)exp((double)dw);   /* exactly-rounded fp32 exp */
    float eh = (float)exp((double)dh);
    float wb = __fmul_rn(ew, wa);
    float hb = __fmul_rn(eh, ha);
    float x1 = __fsub_rn(cx, __fmul_rn(0.5f, wb));
    float y1 = __fsub_rn(cy, __fmul_rn(0.5f, hb));
    float x2 = __fadd_rn(cx, __fmul_rn(0.5f, wb));
    float y2 = __fadd_rn(cy, __fmul_rn(0.5f, hb));
    x1 = fminf(fmaxf(x1, 0.f), IMGSZ);
    y1 = fminf(fmaxf(y1, 0.f), IMGSZ);
    x2 = fminf(fmaxf(x2, 0.f), IMGSZ);
    y2 = fminf(fmaxf(y2, 0.f), IMGSZ);
    reinterpret_cast<float4*>(g_boxes)[j] = make_float4(x1, y1, x2, y2);
    g_valid[j] = (__fsub_rn(x2, x1) >= MINSZ) && (__fsub_rn(y2, y1) >= MINSZ);
}

/* ----------- NMS suppression mask — exact fp32, UNFUSED (match XLA) -------- */
__global__ void nms_mask_kernel() {
    int rb = blockIdx.y, cb = blockIdx.x;
    int t = threadIdx.x;
    __shared__ float4 cbox[64];
    int j0 = cb * 64;
    int jg = j0 + t;
    cbox[t] = (jg < PRE) ? reinterpret_cast<const float4*>(g_boxes)[jg]
                         : make_float4(0.f, 0.f, 0.f, 0.f);
    __syncthreads();
    int i = rb * 64 + t;
    if (i >= PRE) return;
    unsigned long long bits = 0ull;
    if (j0 + 63 > i) {
        float4 b = reinterpret_cast<const float4*>(g_boxes)[i];
        float a1 = __fmul_rn(__fsub_rn(b.z, b.x), __fsub_rn(b.w, b.y));
        int jmax = min(64, PRE - j0);
        for (int jj = 0; jj < jmax; jj++) {
            int j = j0 + jj;
            if (j <= i) continue;
            float4 c = cbox[jj];
            float lx = fmaxf(b.x, c.x), ly = fmaxf(b.y, c.y);
            float rx = fminf(b.z, c.z), ry = fminf(b.w, c.w);
            float iw = fmaxf(__fsub_rn(rx, lx), 0.f);
            float ih = fmaxf(__fsub_rn(ry, ly), 0.f);
            float inter = __fmul_rn(iw, ih);
            float a2 = __fmul_rn(__fsub_rn(c.z, c.x), __fsub_rn(c.w, c.y));
            float den = fmaxf(__fsub_rn(__fadd_rn(a1, a2), inter), 1e-6f);
            float iou = __fdiv_rn(inter, den);
            if (iou > NMS_THR) bits |= (1ull << jj);
        }
    }
    g_mask[(size_t)i * MASKW + cb] = bits;
}

/* -------- greedy scan: one warp, register-resident remaining-mask ---------- */
__global__ void nms_scan_kernel(float* __restrict__ out) {
    int lane = threadIdx.x;  /* 32 threads */
    for (int i = lane; i < POST * 4; i += 32) out[i] = 0.f;

    /* lane owns words lane, lane+32, lane+64; bit set = suppressed/invalid */
    unsigned long long rem0, rem1, rem2;
    {
        unsigned long long m[3];
#pragma unroll
        for (int q = 0; q < 3; q++) {
            int w = lane + q * 32;
            unsigned long long v = ~0ull;
            if (w < MASKW) {
                v = 0ull;
                int base = w * 64;
#pragma unroll 4
                for (int k = 0; k < 64; k++) {
                    int j = base + k;
                    if (j >= PRE || !g_valid[j]) v |= (1ull << k);
                }
            }
            m[q] = v;
        }
        rem0 = m[0]; rem1 = m[1]; rem2 = m[2];
    }

    int nkept = 0;
    int curw = 0;
    unsigned long long curmask = ~0ull;   /* positions still eligible in curw */
    while (nkept < POST && curw < MASKW) {
        int owner = curw & 31;
        int q = curw >> 5;                 /* uniform across warp */
        unsigned long long myv = (q == 0) ? rem0 : (q == 1) ? rem1 : rem2;
        unsigned long long wv = (~__shfl_sync(0xffffffffu, myv, owner)) & curmask;
        if (wv == 0ull) { curw++; curmask = ~0ull; continue; }
        int bit = __ffsll((long long)wv) - 1;
        int i = curw * 64 + bit;
        if (lane < 4) out[nkept * 4 + lane] = g_boxes[i * 4 + lane];
        nkept++;
        const unsigned long long* row = &g_mask[(size_t)i * MASKW];
        if (lane < MASKW)      rem0 |= row[lane];
        if (lane + 32 < MASKW) rem1 |= row[lane + 32];
        if (lane + 64 < MASKW) rem2 |= row[lane + 64];
        if (bit == 63) { curw++; curmask = ~0ull; }
        else           { curmask = (~0ull) << (bit + 1); }
    }
}

/* --------------------------------- launch ---------------------------------- */
extern "C" void kernel_launch(void* const* d_in, const int* in_sizes, int n_in,
                              void* d_out, int out_size) {
    (void)in_sizes; (void)n_in; (void)out_size;
    const float* feature = (const float*)d_in[0];
    const float* anchors = (const float*)d_in[1];
    const float* w_conv  = (const float*)d_in[2];
    const float* b_conv  = (const float*)d_in[3];
    const float* w_obj   = (const float*)d_in[4];
    const float* b_obj   = (const float*)d_in[5];
    const float* w_reg   = (const float*)d_in[6];
    const float* b_reg   = (const float*)d_in[7];
    float* out = (float*)d_out;

    cudaFuncSetAttribute(sort_kernel, cudaFuncAttributeMaxDynamicSharedMemorySize, 65536);

    zero_kernel<<<256, 256>>>();
    transpose_w_kernel<<<(KTOT * 256 + 255) / 256, 256>>>(w_conv);
    conv3x3_kernel<<<dim3(313, 2), 256>>>(feature, b_conv);
    heads_kernel<<<157, 256>>>(w_obj, b_obj, w_reg, b_reg);
    select_kernel<<<1, 1024>>>(0);
    hist2_kernel<<<1407, 256>>>();
    select_kernel<<<1, 1024>>>(1);
    compact_kernel<<<1407, 256>>>();
    finalize_kernel<<<1, 1024>>>();
    sort_kernel<<<1, 1024, 65536>>>();
    decode_kernel<<<24, 256>>>(anchors);
    nms_mask_kernel<<<dim3(94, 94), 64>>>();
    nms_scan_kernel<<<1, 32>>>(out);
}

// round 7
// speedup vs baseline: 1.9070x; 1.4283x over previous
#include <cuda_runtime.h>
#include <math.h>
#include <stdint.h>

#define C_IN   256
#define HGT    200
#define WID    200
#define HWNUM  40000
#define NA     9
#define KTOT   2304
#define NSCORE 360000
#define PRE    6000
#define POST   1000
#define IMGSZ  1600.0f
#define NMS_THR 0.7f
#define MINSZ  1.0f
#define BCLIP  4.135166556742356f   /* log(1000/16) */
#define MASKW  94                   /* ceil(6000/64) */

/* ------------------------- scratch (device globals) ------------------------ */
__device__ float              g_wT[KTOT * 256];           /* w transposed: [k'][m] */
__device__ float              g_t[C_IN * HWNUM];          /* conv output (relu'd) */
__device__ unsigned int       g_keys[NSCORE];             /* monotone score keys  */
__device__ float              g_deltas[NSCORE * 4];
__device__ int                g_hist1[65536];
__device__ int                g_hist2[65536];
__device__ int                g_selHigh;
__device__ int                g_cntAbove1;
__device__ unsigned int       g_T;
__device__ int                g_nAbove;
__device__ int                g_cntHigh;
__device__ int                g_cntEq;
__device__ unsigned int       g_tieIdx[8192];
__device__ unsigned long long g_list[8192];               /* (key<<32)|(~idx)     */
__device__ float              g_boxes[PRE * 4];
__device__ int                g_valid[PRE];
__device__ unsigned long long g_mask[(size_t)PRE * MASKW];

/* --------------------------------- zero ----------------------------------- */
__global__ void zero_kernel() {
    int i = blockIdx.x * blockDim.x + threadIdx.x;
    if (i < 65536) { g_hist1[i] = 0; g_hist2[i] = 0; }
    if (i == 0) { g_cntHigh = 0; g_cntEq = 0; }
}

/* ------------- one-time weight transpose: wT[k'][m], k'=(rs,ci) ------------ */
__global__ void transpose_w_kernel(const float* __restrict__ w) {
    int idx = blockIdx.x * blockDim.x + threadIdx.x;   /* write-coalesced in m */
    if (idx >= KTOT * 256) return;
    int kp = idx >> 8;          /* k' = rs*256 + ci */
    int m  = idx & 255;
    int ci = kp & 255;
    int rs = kp >> 8;
    g_wT[idx] = w[(size_t)m * KTOT + ci * 9 + rs];
}

/* ---- 3x3 conv (implicit GEMM, sequential FMA over k' = (r,s,ci) order) ---- */
/* Bit-exact anchor: one accumulator per output, k' stepped 0..2303 ascending. */
/* B-columns per thread: {tx*4..+3, 64+tx*4..+3} -> conflict-free LDS.128.     */
__global__ __launch_bounds__(256, 2)
void conv3x3_kernel(const float* __restrict__ x, const float* __restrict__ bias) {
    __shared__ float As[2][8][128];
    __shared__ float Bs[2][8][128];
    const int tid = threadIdx.x;
    const int m0 = blockIdx.y * 128;
    const int p0 = blockIdx.x * 128;
    const int kr = tid >> 5;           /* 0..7   : k-row within tile   */
    const int lc = (tid & 31) * 4;     /* 0..124 : column (m or p)     */
    const int tx = tid & 15, ty = tid >> 4;

    float4 aReg = make_float4(0.f, 0.f, 0.f, 0.f);
    float4 bReg = make_float4(0.f, 0.f, 0.f, 0.f);

    auto loadTiles = [&](int it) {
        int k0 = it * 8;
        aReg = *reinterpret_cast<const float4*>(&g_wT[(size_t)(k0 + kr) * 256 + m0 + lc]);
        int kp = k0 + kr;
        int rs = kp >> 8;
        int ci = kp & 255;
        int r = rs / 3 - 1;
        int s = rs - (rs / 3) * 3 - 1;
        const float* base = x + (size_t)ci * HWNUM;
        float bv[4];
#pragma unroll
        for (int jj = 0; jj < 4; jj++) {
            int p = p0 + lc + jj;
            float v = 0.f;
            if (p < HWNUM) {
                int h = p / 200;
                int wc = p - h * 200;
                int hh = h + r, wcc = wc + s;
                if (hh >= 0 && hh < HGT && wcc >= 0 && wcc < WID)
                    v = base[hh * WID + wcc];
            }
            bv[jj] = v;
        }
        bReg = make_float4(bv[0], bv[1], bv[2], bv[3]);
    };
    auto storeTiles = [&](int buf) {
        *reinterpret_cast<float4*>(&As[buf][kr][lc]) = aReg;
        *reinterpret_cast<float4*>(&Bs[buf][kr][lc]) = bReg;
    };

    float acc[8][8];
#pragma unroll
    for (int i = 0; i < 8; i++)
#pragma unroll
        for (int j = 0; j < 8; j++) acc[i][j] = 0.f;

    loadTiles(0);
    storeTiles(0);
    __syncthreads();
    int cur = 0;
    const int NIT = KTOT / 8;  /* 288 */
    for (int it = 0; it < NIT; it++) {
        if (it + 1 < NIT) loadTiles(it + 1);
#pragma unroll
        for (int kk = 0; kk < 8; kk++) {
            float4 a0 = *reinterpret_cast<const float4*>(&As[cur][kk][ty * 8]);
            float4 a1 = *reinterpret_cast<const float4*>(&As[cur][kk][ty * 8 + 4]);
            float4 b0 = *reinterpret_cast<const float4*>(&Bs[cur][kk][tx * 4]);
            float4 b1 = *reinterpret_cast<const float4*>(&Bs[cur][kk][64 + tx * 4]);
            float av[8] = {a0.x, a0.y, a0.z, a0.w, a1.x, a1.y, a1.z, a1.w};
            float bv[8] = {b0.x, b0.y, b0.z, b0.w, b1.x, b1.y, b1.z, b1.w};
#pragma unroll
            for (int i = 0; i < 8; i++)
#pragma unroll
                for (int j = 0; j < 8; j++)
                    acc[i][j] = fmaf(av[i], bv[j], acc[i][j]);
        }
        if (it + 1 < NIT) {
            storeTiles(cur ^ 1);
            __syncthreads();
            cur ^= 1;
        }
    }
    /* epilogue: columns are p0+tx*4 (jj 0-3) and p0+64+tx*4 (jj 4-7) */
#pragma unroll
    for (int i = 0; i < 8; i++) {
        int m = m0 + ty * 8 + i;
        float bv = bias[m];
        float4 o0, o1;
        o0.x = fmaxf(__fadd_rn(acc[i][0], bv), 0.f);
        o0.y = fmaxf(__fadd_rn(acc[i][1], bv), 0.f);
        o0.z = fmaxf(__fadd_rn(acc[i][2], bv), 0.f);
        o0.w = fmaxf(__fadd_rn(acc[i][3], bv), 0.f);
        o1.x = fmaxf(__fadd_rn(acc[i][4], bv), 0.f);
        o1.y = fmaxf(__fadd_rn(acc[i][5], bv), 0.f);
        o1.z = fmaxf(__fadd_rn(acc[i][6], bv), 0.f);
        o1.w = fmaxf(__fadd_rn(acc[i][7], bv), 0.f);
        int pA = p0 + tx * 4;
        int pB = p0 + 64 + tx * 4;
        if (pA < HWNUM) *reinterpret_cast<float4*>(&g_t[(size_t)m * HWNUM + pA]) = o0;
        if (pB < HWNUM) *reinterpret_cast<float4*>(&g_t[(size_t)m * HWNUM + pB]) = o1;
    }
}

/* --- 1x1 heads (plain sequential FMA) + fused hist1; 128 thr, 313 blocks --- */
__global__ __launch_bounds__(128)
void heads_kernel(const float* __restrict__ wObj, const float* __restrict__ bObj,
                  const float* __restrict__ wReg, const float* __restrict__ bReg) {
    __shared__ float ws[45 * 256];
    __shared__ float bs[45];
    int tid = threadIdx.x;
    for (int i = tid; i < 9 * 256; i += 128) ws[i] = wObj[i];
    for (int i = tid; i < 36 * 256; i += 128) ws[9 * 256 + i] = wReg[i];
    if (tid < 9) bs[tid] = bObj[tid];
    if (tid < 36) bs[9 + tid] = bReg[tid];
    __syncthreads();

    int p = blockIdx.x * 128 + tid;
    if (p >= HWNUM) return;
    float acc[45];
#pragma unroll
    for (int o = 0; o < 45; o++) acc[o] = 0.f;
#pragma unroll 4
    for (int ci = 0; ci < 256; ci++) {
        float a = g_t[(size_t)ci * HWNUM + p];
#pragma unroll
        for (int o = 0; o < 45; o++)
            acc[o] = fmaf(a, ws[o * 256 + ci], acc[o]);
    }
#pragma unroll
    for (int a = 0; a < 9; a++) {
        float s = __fadd_rn(acc[a], bs[a]);
        unsigned u = __float_as_uint(s);
        unsigned key = (u & 0x80000000u) ? ~u : (u | 0x80000000u);
        g_keys[p * 9 + a] = key;
        atomicAdd(&g_hist1[key >> 16], 1);
    }
#pragma unroll
    for (int c = 0; c < 36; c++)
        g_deltas[(size_t)p * 36 + c] = __fadd_rn(acc[9 + c], bs[9 + c]);
}

/* ------------------------------ radix select ------------------------------- */
__global__ void select_kernel(int pass) {
    const int* hist = (pass == 0) ? g_hist1 : g_hist2;
    __shared__ int csum[1024];
    __shared__ int sbase;
    int t = threadIdx.x;
    if (t == 0) sbase = (pass == 0) ? 0 : g_cntAbove1;
    __syncthreads();
    int base = sbase;
    int s = 0;
    int start = t * 64;
    for (int k = 0; k < 64; k++) s += hist[65535 - (start + k)];
    csum[t] = s;
    __syncthreads();
    for (int off = 1; off < 1024; off <<= 1) {
        int v = (t >= off) ? csum[t - off] : 0;
        __syncthreads();
        csum[t] += v;
        __syncthreads();
    }
    int incl = csum[t];
    int excl = incl - s;
    if (base + excl < PRE && base + incl >= PRE) {
        int acc = base + excl;
        for (int k = 0; k < 64; k++) {
            int b = 65535 - (start + k);
            int c = hist[b];
            if (acc + c >= PRE) {
                if (pass == 0) { g_selHigh = b; g_cntAbove1 = acc; }
                else { g_T = (((unsigned)g_selHigh) << 16) | (unsigned)b; g_nAbove = acc; }
                break;
            }
            acc += c;
        }
    }
}

__global__ void hist2_kernel() {
    int i = blockIdx.x * blockDim.x + threadIdx.x;
    if (i < NSCORE) {
        unsigned k = g_keys[i];
        if ((int)(k >> 16) == g_selHigh) atomicAdd(&g_hist2[k & 0xFFFFu], 1);
    }
}

__global__ void compact_kernel() {
    int i = blockIdx.x * blockDim.x + threadIdx.x;
    if (i >= NSCORE) return;
    unsigned k = g_keys[i];
    unsigned T = g_T;
    if (k > T) {
        int pos = atomicAdd(&g_cntHigh, 1);
        g_list[pos] = (((unsigned long long)k) << 32) |
                      (unsigned long long)(0xFFFFFFFFu - (unsigned)i);
    } else if (k == T) {
        int pos = atomicAdd(&g_cntEq, 1);
        if (pos < 8192) g_tieIdx[pos] = (unsigned)i;
    }
}

/* sort tie indices ascending (bitonic bounded by next-pow2), append, pad */
__global__ void finalize_kernel() {
    __shared__ unsigned sIdx[8192];
    int t = threadIdx.x;
    int cnt = g_cntEq; if (cnt > 8192) cnt = 8192;
    int need = PRE - g_nAbove;
    int n2 = 32;
    while (n2 < cnt) n2 <<= 1;
    for (int i = t; i < n2; i += 1024) sIdx[i] = (i < cnt) ? g_tieIdx[i] : 0xFFFFFFFFu;
    __syncthreads();
    for (int k = 2; k <= n2; k <<= 1)
        for (int j = k >> 1; j > 0; j >>= 1) {
            for (int i = t; i < n2; i += 1024) {
                int l = i ^ j;
                if (l > i) {
                    unsigned a = sIdx[i], b = sIdx[l];
                    bool up = ((i & k) == 0);
                    if ((a > b) == up) { sIdx[i] = b; sIdx[l] = a; }
                }
            }
            __syncthreads();
        }
    unsigned T = g_T;
    int nA = g_nAbove;
    for (int j = t; j < need; j += 1024)
        g_list[nA + j] = (((unsigned long long)T) << 32) |
                         (unsigned long long)(0xFFFFFFFFu - sIdx[j]);
    for (int j = PRE + t; j < 8192; j += 1024) g_list[j] = 0ull;
}

/* descending bitonic sort of the 8192 composites (zeros sink to the end) */
__global__ void sort_kernel() {
    extern __shared__ unsigned long long sm[];
    int t = threadIdx.x;
    for (int i = t; i < 8192; i += 1024) sm[i] = g_list[i];
    __syncthreads();
    for (int k = 2; k <= 8192; k <<= 1)
        for (int j = k >> 1; j > 0; j >>= 1) {
            for (int i = t; i < 8192; i += 1024) {
                int l = i ^ j;
                if (l > i) {
                    unsigned long long a = sm[i], b = sm[l];
                    bool up = ((i & k) == 0);
                    if ((a < b) == up) { sm[i] = b; sm[l] = a; }
                }
            }
            __syncthreads();
        }
    for (int i = t; i < 8192; i += 1024) g_list[i] = sm[i];
}

/* ---------------- decode/clip — exact fp32, UNFUSED (match XLA) ------------ */
__global__ void decode_kernel(const float* __restrict__ anchors) {
    int j = blockIdx.x * blockDim.x + threadIdx.x;
    if (j >= PRE) return;
    unsigned long long comp = g_list[j];
    unsigned idx = 0xFFFFFFFFu - (unsigned)(comp & 0xFFFFFFFFull);
    float4 an = reinterpret_cast<const float4*>(anchors)[idx];
    float4 dl = reinterpret_cast<const float4*>(g_deltas)[idx];
    float wa = __fsub_rn(an.z, an.x);
    float ha = __fsub_rn(an.w, an.y);
    float xa = __fadd_rn(an.x, __fmul_rn(0.5f, wa));
    float ya = __fadd_rn(an.y, __fmul_rn(0.5f, ha));
    float dw = fminf(dl.z, BCLIP), dh = fminf(dl.w, BCLIP);
    float cx = __fadd_rn(__fmul_rn(dl.x, wa), xa);
    float cy = __fadd_rn(__fmul_rn(dl.y, ha), ya);
    float ew = (float)exp((double)dw);   /* exactly-rounded fp32 exp */
    float eh = (float)exp((double)dh);
    float wb = __fmul_rn(ew, wa);
    float hb = __fmul_rn(eh, ha);
    float x1 = __fsub_rn(cx, __fmul_rn(0.5f, wb));
    float y1 = __fsub_rn(cy, __fmul_rn(0.5f, hb));
    float x2 = __fadd_rn(cx, __fmul_rn(0.5f, wb));
    float y2 = __fadd_rn(cy, __fmul_rn(0.5f, hb));
    x1 = fminf(fmaxf(x1, 0.f), IMGSZ);
    y1 = fminf(fmaxf(y1, 0.f), IMGSZ);
    x2 = fminf(fmaxf(x2, 0.f), IMGSZ);
    y2 = fminf(fmaxf(y2, 0.f), IMGSZ);
    reinterpret_cast<float4*>(g_boxes)[j] = make_float4(x1, y1, x2, y2);
    g_valid[j] = (__fsub_rn(x2, x1) >= MINSZ) && (__fsub_rn(y2, y1) >= MINSZ);
}

/* ----------- NMS suppression mask — exact fp32, UNFUSED (match XLA) -------- */
__global__ void nms_mask_kernel() {
    int rb = blockIdx.y, cb = blockIdx.x;
    int t = threadIdx.x;
    __shared__ float4 cbox[64];
    int j0 = cb * 64;
    int jg = j0 + t;
    cbox[t] = (jg < PRE) ? reinterpret_cast<const float4*>(g_boxes)[jg]
                         : make_float4(0.f, 0.f, 0.f, 0.f);
    __syncthreads();
    int i = rb * 64 + t;
    if (i >= PRE) return;
    unsigned long long bits = 0ull;
    if (j0 + 63 > i) {
        float4 b = reinterpret_cast<const float4*>(g_boxes)[i];
        float a1 = __fmul_rn(__fsub_rn(b.z, b.x), __fsub_rn(b.w, b.y));
        int jmax = min(64, PRE - j0);
        for (int jj = 0; jj < jmax; jj++) {
            int j = j0 + jj;
            if (j <= i) continue;
            float4 c = cbox[jj];
            float lx = fmaxf(b.x, c.x), ly = fmaxf(b.y, c.y);
            float rx = fminf(b.z, c.z), ry = fminf(b.w, c.w);
            float iw = fmaxf(__fsub_rn(rx, lx), 0.f);
            float ih = fmaxf(__fsub_rn(ry, ly), 0.f);
            float inter = __fmul_rn(iw, ih);
            float a2 = __fmul_rn(__fsub_rn(c.z, c.x), __fsub_rn(c.w, c.y));
            float den = fmaxf(__fsub_rn(__fadd_rn(a1, a2), inter), 1e-6f);
            float iou = __fdiv_rn(inter, den);
            if (iou > NMS_THR) bits |= (1ull << jj);
        }
    }
    g_mask[(size_t)i * MASKW + cb] = bits;
}

/* ------ greedy scan: chunked smem prefetch (256 thr) + warp-0 serial ------- */
#define CHUNK 64
__global__ void nms_scan_kernel(float* __restrict__ out) {
    extern __shared__ unsigned long long sm2[];
    unsigned long long (*rows)[MASKW] =
        reinterpret_cast<unsigned long long (*)[MASKW]>(sm2);
    volatile unsigned long long* rem = sm2 + CHUNK * MASKW;  /* 94 words */
    __shared__ int s_nkept;
    int tid = threadIdx.x;
    for (int i = tid; i < POST * 4; i += 256) out[i] = 0.f;
    for (int w = tid; w < MASKW; w += 256) {
        unsigned long long m = 0ull;
        int base = w * 64;
        for (int k = 0; k < 64; k++) {
            int j = base + k;
            if (j >= PRE || !g_valid[j]) m |= (1ull << k);
        }
        rem[w] = m;
    }
    if (tid == 0) s_nkept = 0;
    __syncthreads();

    for (int c = 0; c < MASKW; c++) {
        int base_i = c * CHUNK;
        /* prefetch 64 mask rows into smem */
        for (int idx = tid; idx < CHUNK * MASKW; idx += 256) {
            int rr = idx / MASKW, col = idx - rr * MASKW;
            int gi = base_i + rr;
            rows[rr][col] = (gi < PRE) ? g_mask[(size_t)gi * MASKW + col] : 0ull;
        }
        __syncthreads();
        if (tid < 32) {
            int lane = tid;
            int nk = s_nkept;
            for (int bit = 0; bit < CHUNK; bit++) {
                int i = base_i + bit;
                if (i >= PRE || nk >= POST) break;
                if (!((rem[c] >> bit) & 1ull)) {
                    if (lane < 4) out[nk * 4 + lane] = g_boxes[i * 4 + lane];
                    nk++;
                    for (int w = c + lane; w < MASKW; w += 32)
                        rem[w] = rem[w] | rows[bit][w];
                    __syncwarp();
                }
            }
            if (lane == 0) s_nkept = nk;
        }
        __syncthreads();
        if (s_nkept >= POST) break;
        __syncthreads();
    }
}

/* --------------------------------- launch ---------------------------------- */
extern "C" void kernel_launch(void* const* d_in, const int* in_sizes, int n_in,
                              void* d_out, int out_size) {
    (void)in_sizes; (void)n_in; (void)out_size;
    const float* feature = (const float*)d_in[0];
    const float* anchors = (const float*)d_in[1];
    const float* w_conv  = (const float*)d_in[2];
    const float* b_conv  = (const float*)d_in[3];
    const float* w_obj   = (const float*)d_in[4];
    const float* b_obj   = (const float*)d_in[5];
    const float* w_reg   = (const float*)d_in[6];
    const float* b_reg   = (const float*)d_in[7];
    float* out = (float*)d_out;

    cudaFuncSetAttribute(sort_kernel, cudaFuncAttributeMaxDynamicSharedMemorySize, 65536);
    cudaFuncSetAttribute(nms_scan_kernel, cudaFuncAttributeMaxDynamicSharedMemorySize, 65536);

    zero_kernel<<<256, 256>>>();
    transpose_w_kernel<<<(KTOT * 256 + 255) / 256, 256>>>(w_conv);
    conv3x3_kernel<<<dim3(313, 2), 256>>>(feature, b_conv);
    heads_kernel<<<313, 128>>>(w_obj, b_obj, w_reg, b_reg);
    select_kernel<<<1, 1024>>>(0);
    hist2_kernel<<<1407, 256>>>();
    select_kernel<<<1, 1024>>>(1);
    compact_kernel<<<1407, 256>>>();
    finalize_kernel<<<1, 1024>>>();
    sort_kernel<<<1, 1024, 65536>>>();
    decode_kernel<<<24, 256>>>(anchors);
    nms_mask_kernel<<<dim3(94, 94), 64>>>();
    nms_scan_kernel<<<1, 256, (CHUNK * MASKW + MASKW) * 8>>>(out);
}

// round 9
// speedup vs baseline: 1.9291x; 1.0116x over previous
#include <cuda_runtime.h>
#include <math.h>
#include <stdint.h>

#define C_IN   256
#define HGT    200
#define WID    200
#define HWNUM  40000
#define NA     9
#define KTOT   2304
#define NSCORE 360000
#define PRE    6000
#define POST   1000
#define IMGSZ  1600.0f
#define NMS_THR 0.7f
#define MINSZ  1.0f
#define BCLIP  4.135166556742356f   /* log(1000/16) */
#define MASKW  94                   /* ceil(6000/64) */

/* ------------------------- scratch (device globals) ------------------------ */
__device__ float              g_wT[KTOT * 256];           /* w transposed: [k'][m] */
__device__ float              g_t[C_IN * HWNUM];          /* conv output (relu'd) */
__device__ unsigned int       g_keys[NSCORE];             /* monotone score keys  */
__device__ float              g_deltas[NSCORE * 4];
__device__ int                g_hist1[65536];
__device__ int                g_hist2[65536];
__device__ int                g_selHigh;
__device__ int                g_cntAbove1;
__device__ unsigned int       g_T;
__device__ int                g_nAbove;
__device__ int                g_cntHigh;
__device__ int                g_cntEq;
__device__ unsigned int       g_tieIdx[8192];
__device__ unsigned long long g_list[8192];               /* (key<<32)|(~idx)     */
__device__ float              g_boxes[PRE * 4];
__device__ int                g_valid[PRE];
__device__ unsigned long long g_mask[(size_t)PRE * MASKW];

/* --------------------------------- zero ----------------------------------- */
__global__ void zero_kernel() {
    int i = blockIdx.x * blockDim.x + threadIdx.x;
    if (i < 65536) { g_hist1[i] = 0; g_hist2[i] = 0; }
    if (i == 0) { g_cntHigh = 0; g_cntEq = 0; }
}

/* ------------- one-time weight transpose: wT[k'][m], k'=(rs,ci) ------------ */
__global__ void transpose_w_kernel(const float* __restrict__ w) {
    int idx = blockIdx.x * blockDim.x + threadIdx.x;   /* write-coalesced in m */
    if (idx >= KTOT * 256) return;
    int kp = idx >> 8;          /* k' = rs*256 + ci */
    int m  = idx & 255;
    int ci = kp & 255;
    int rs = kp >> 8;
    g_wT[idx] = w[(size_t)m * KTOT + ci * 9 + rs];
}

/* ---- 3x3 conv (implicit GEMM, sequential FMA over k' = (r,s,ci) order) ---- */
/* Bit-exact anchor preserved: each output element accumulates k'=0..2303      */
/* strictly in order. Inner product pairs adjacent j-columns into one          */
/* fma.rn.f32x2 (each half rounded RN identically to scalar FFMA).             */
__global__ __launch_bounds__(256, 2)
void conv3x3_kernel(const float* __restrict__ x, const float* __restrict__ bias) {
    __shared__ __align__(16) float As[2][8][128];
    __shared__ __align__(16) float Bs[2][8][128];
    const int tid = threadIdx.x;
    const int m0 = blockIdx.y * 128;
    const int p0 = blockIdx.x * 128;
    const int kr = tid >> 5;           /* 0..7   : k-row within tile   */
    const int lc = (tid & 31) * 4;     /* 0..124 : column (m or p)     */
    const int tx = tid & 15, ty = tid >> 4;

    float4 aReg = make_float4(0.f, 0.f, 0.f, 0.f);
    float4 bReg = make_float4(0.f, 0.f, 0.f, 0.f);

    auto loadTiles = [&](int it) {
        int k0 = it * 8;
        aReg = *reinterpret_cast<const float4*>(&g_wT[(size_t)(k0 + kr) * 256 + m0 + lc]);
        int kp = k0 + kr;
        int rs = kp >> 8;
        int ci = kp & 255;
        int r = rs / 3 - 1;
        int s = rs - (rs / 3) * 3 - 1;
        const float* base = x + (size_t)ci * HWNUM;
        float bv[4];
#pragma unroll
        for (int jj = 0; jj < 4; jj++) {
            int p = p0 + lc + jj;
            float v = 0.f;
            if (p < HWNUM) {
                int h = p / 200;
                int wc = p - h * 200;
                int hh = h + r, wcc = wc + s;
                if (hh >= 0 && hh < HGT && wcc >= 0 && wcc < WID)
                    v = base[hh * WID + wcc];
            }
            bv[jj] = v;
        }
        bReg = make_float4(bv[0], bv[1], bv[2], bv[3]);
    };
    auto storeTiles = [&](int buf) {
        *reinterpret_cast<float4*>(&As[buf][kr][lc]) = aReg;
        *reinterpret_cast<float4*>(&Bs[buf][kr][lc]) = bReg;
    };

    unsigned long long acc2[8][4];
#pragma unroll
    for (int i = 0; i < 8; i++)
#pragma unroll
        for (int j = 0; j < 4; j++) acc2[i][j] = 0ull;

    loadTiles(0);
    storeTiles(0);
    __syncthreads();
    int cur = 0;
    const int NIT = KTOT / 8;  /* 288 */
    for (int it = 0; it < NIT; it++) {
        if (it + 1 < NIT) loadTiles(it + 1);
#pragma unroll
        for (int kk = 0; kk < 8; kk++) {
            float4 a0 = *reinterpret_cast<const float4*>(&As[cur][kk][ty * 8]);
            float4 a1 = *reinterpret_cast<const float4*>(&As[cur][kk][ty * 8 + 4]);
            ulonglong2 bb0 = *reinterpret_cast<const ulonglong2*>(&Bs[cur][kk][tx * 4]);
            ulonglong2 bb1 = *reinterpret_cast<const ulonglong2*>(&Bs[cur][kk][64 + tx * 4]);
            unsigned long long b2[4] = {bb0.x, bb0.y, bb1.x, bb1.y};
            float av[8] = {a0.x, a0.y, a0.z, a0.w, a1.x, a1.y, a1.z, a1.w};
            unsigned long long a2[8];
#pragma unroll
            for (int i = 0; i < 8; i++) {
                unsigned ai = __float_as_uint(av[i]);
                asm("mov.b64 %0, {%1, %1};" : "=l"(a2[i]) : "r"(ai));
            }
#pragma unroll
            for (int i = 0; i < 8; i++)
#pragma unroll
                for (int j = 0; j < 4; j++)
                    asm("fma.rn.f32x2 %0, %1, %2, %3;"
                        : "=l"(acc2[i][j])
                        : "l"(a2[i]), "l"(b2[j]), "l"(acc2[i][j]));
        }
        if (it + 1 < NIT) {
            storeTiles(cur ^ 1);
            __syncthreads();
            cur ^= 1;
        }
    }
    /* epilogue: unpack pairs; columns p0+tx*4 (j 0-1) and p0+64+tx*4 (j 2-3) */
#pragma unroll
    for (int i = 0; i < 8; i++) {
        int m = m0 + ty * 8 + i;
        float bv = bias[m];
        float v[8];
#pragma unroll
        for (int j = 0; j < 4; j++) {
            unsigned lo, hi;
            asm("mov.b64 {%0, %1}, %2;" : "=r"(lo), "=r"(hi) : "l"(acc2[i][j]));
            v[j * 2 + 0] = __uint_as_float(lo);
            v[j * 2 + 1] = __uint_as_float(hi);
        }
        float4 o0, o1;
        o0.x = fmaxf(__fadd_rn(v[0], bv), 0.f);
        o0.y = fmaxf(__fadd_rn(v[1], bv), 0.f);
        o0.z = fmaxf(__fadd_rn(v[2], bv), 0.f);
        o0.w = fmaxf(__fadd_rn(v[3], bv), 0.f);
        o1.x = fmaxf(__fadd_rn(v[4], bv), 0.f);
        o1.y = fmaxf(__fadd_rn(v[5], bv), 0.f);
        o1.z = fmaxf(__fadd_rn(v[6], bv), 0.f);
        o1.w = fmaxf(__fadd_rn(v[7], bv), 0.f);
        int pA = p0 + tx * 4;
        int pB = p0 + 64 + tx * 4;
        if (pA < HWNUM) *reinterpret_cast<float4*>(&g_t[(size_t)m * HWNUM + pA]) = o0;
        if (pB < HWNUM) *reinterpret_cast<float4*>(&g_t[(size_t)m * HWNUM + pB]) = o1;
    }
}

/* --- 1x1 heads (plain sequential FMA) + fused hist1; 128 thr, 313 blocks --- */
__global__ __launch_bounds__(128)
void heads_kernel(const float* __restrict__ wObj, const float* __restrict__ bObj,
                  const float* __restrict__ wReg, const float* __restrict__ bReg) {
    __shared__ float ws[45 * 256];
    __shared__ float bs[45];
    int tid = threadIdx.x;
    for (int i = tid; i < 9 * 256; i += 128) ws[i] = wObj[i];
    for (int i = tid; i < 36 * 256; i += 128) ws[9 * 256 + i] = wReg[i];
    if (tid < 9) bs[tid] = bObj[tid];
    if (tid < 36) bs[9 + tid] = bReg[tid];
    __syncthreads();

    int p = blockIdx.x * 128 + tid;
    if (p >= HWNUM) return;
    float acc[45];
#pragma unroll
    for (int o = 0; o < 45; o++) acc[o] = 0.f;
#pragma unroll 4
    for (int ci = 0; ci < 256; ci++) {
        float a = g_t[(size_t)ci * HWNUM + p];
#pragma unroll
        for (int o = 0; o < 45; o++)
            acc[o] = fmaf(a, ws[o * 256 + ci], acc[o]);
    }
#pragma unroll
    for (int a = 0; a < 9; a++) {
        float s = __fadd_rn(acc[a], bs[a]);
        unsigned u = __float_as_uint(s);
        unsigned key = (u & 0x80000000u) ? ~u : (u | 0x80000000u);
        g_keys[p * 9 + a] = key;
        atomicAdd(&g_hist1[key >> 16], 1);
    }
#pragma unroll
    for (int c = 0; c < 36; c++)
        g_deltas[(size_t)p * 36 + c] = __fadd_rn(acc[9 + c], bs[9 + c]);
}

/* ------------------------------ radix select ------------------------------- */
__global__ void select_kernel(int pass) {
    const int* hist = (pass == 0) ? g_hist1 : g_hist2;
    __shared__ int csum[1024];
    __shared__ int sbase;
    int t = threadIdx.x;
    if (t == 0) sbase = (pass == 0) ? 0 : g_cntAbove1;
    __syncthreads();
    int base = sbase;
    int s = 0;
    int start = t * 64;
    for (int k = 0; k < 64; k++) s += hist[65535 - (start + k)];
    csum[t] = s;
    __syncthreads();
    for (int off = 1; off < 1024; off <<= 1) {
        int v = (t >= off) ? csum[t - off] : 0;
        __syncthreads();
        csum[t] += v;
        __syncthreads();
    }
    int incl = csum[t];
    int excl = incl - s;
    if (base + excl < PRE && base + incl >= PRE) {
        int acc = base + excl;
        for (int k = 0; k < 64; k++) {
            int b = 65535 - (start + k);
            int c = hist[b];
            if (acc + c >= PRE) {
                if (pass == 0) { g_selHigh = b; g_cntAbove1 = acc; }
                else { g_T = (((unsigned)g_selHigh) << 16) | (unsigned)b; g_nAbove = acc; }
                break;
            }
            acc += c;
        }
    }
}

__global__ void hist2_kernel() {
    int i = blockIdx.x * blockDim.x + threadIdx.x;
    if (i < NSCORE) {
        unsigned k = g_keys[i];
        if ((int)(k >> 16) == g_selHigh) atomicAdd(&g_hist2[k & 0xFFFFu], 1);
    }
}

__global__ void compact_kernel() {
    int i = blockIdx.x * blockDim.x + threadIdx.x;
    if (i >= NSCORE) return;
    unsigned k = g_keys[i];
    unsigned T = g_T;
    if (k > T) {
        int pos = atomicAdd(&g_cntHigh, 1);
        g_list[pos] = (((unsigned long long)k) << 32) |
                      (unsigned long long)(0xFFFFFFFFu - (unsigned)i);
    } else if (k == T) {
        int pos = atomicAdd(&g_cntEq, 1);
        if (pos < 8192) g_tieIdx[pos] = (unsigned)i;
    }
}

/* sort tie indices ascending (bitonic bounded by next-pow2), append, pad */
__global__ void finalize_kernel() {
    __shared__ unsigned sIdx[8192];
    int t = threadIdx.x;
    int cnt = g_cntEq; if (cnt > 8192) cnt = 8192;
    int need = PRE - g_nAbove;
    int n2 = 32;
    while (n2 < cnt) n2 <<= 1;
    for (int i = t; i < n2; i += 1024) sIdx[i] = (i < cnt) ? g_tieIdx[i] : 0xFFFFFFFFu;
    __syncthreads();
    for (int k = 2; k <= n2; k <<= 1)
        for (int j = k >> 1; j > 0; j >>= 1) {
            for (int i = t; i < n2; i += 1024) {
                int l = i ^ j;
                if (l > i) {
                    unsigned a = sIdx[i], b = sIdx[l];
                    bool up = ((i & k) == 0);
                    if ((a > b) == up) { sIdx[i] = b; sIdx[l] = a; }
                }
            }
            __syncthreads();
        }
    unsigned T = g_T;
    int nA = g_nAbove;
    for (int j = t; j < need; j += 1024)
        g_list[nA + j] = (((unsigned long long)T) << 32) |
                         (unsigned long long)(0xFFFFFFFFu - sIdx[j]);
    for (int j = PRE + t; j < 8192; j += 1024) g_list[j] = 0ull;
}

/* descending bitonic sort of the 8192 composites (zeros sink to the end) */
__global__ void sort_kernel() {
    extern __shared__ unsigned long long sm[];
    int t = threadIdx.x;
    for (int i = t; i < 8192; i += 1024) sm[i] = g_list[i];
    __syncthreads();
    for (int k = 2; k <= 8192; k <<= 1)
        for (int j = k >> 1; j > 0; j >>= 1) {
            for (int i = t; i < 8192; i += 1024) {
                int l = i ^ j;
                if (l > i) {
                    unsigned long long a = sm[i], b = sm[l];
                    bool up = ((i & k) == 0);
                    if ((a < b) == up) { sm[i] = b; sm[l] = a; }
                }
            }
            __syncthreads();
        }
    for (int i = t; i < 8192; i += 1024) g_list[i] = sm[i];
}

/* ---------------- decode/clip — exact fp32, UNFUSED (match XLA) ------------ */
__global__ void decode_kernel(const float* __restrict__ anchors) {
    int j = blockIdx.x * blockDim.x + threadIdx.x;
    if (j >= PRE) return;
    unsigned long long comp = g_list[j];
    unsigned idx = 0xFFFFFFFFu - (unsigned)(comp & 0xFFFFFFFFull);
    float4 an = reinterpret_cast<const float4*>(anchors)[idx];
    float4 dl = reinterpret_cast<const float4*>(g_deltas)[idx];
    float wa = __fsub_rn(an.z, an.x);
    float ha = __fsub_rn(an.w, an.y);
    float xa = __fadd_rn(an.x, __fmul_rn(0.5f, wa));
    float ya = __fadd_rn(an.y, __fmul_rn(0.5f, ha));
    float dw = fminf(dl.z, BCLIP), dh = fminf(dl.w, BCLIP);
    float cx = __fadd_rn(__fmul_rn(dl.x, wa), xa);
    float cy = __fadd_rn(__fmul_rn(dl.y, ha), ya);
    float ew = (float)exp((double)dw);   /* exactly-rounded fp32 exp */
    float eh = (float)exp((double)dh);
    float wb = __fmul_rn(ew, wa);
    float hb = __fmul_rn(eh, ha);
    float x1 = __fsub_rn(cx, __fmul_rn(0.5f, wb));
    float y1 = __fsub_rn(cy, __fmul_rn(0.5f, hb));
    float x2 = __fadd_rn(cx, __fmul_rn(0.5f, wb));
    float y2 = __fadd_rn(cy, __fmul_rn(0.5f, hb));
    x1 = fminf(fmaxf(x1, 0.f), IMGSZ);
    y1 = fminf(fmaxf(y1, 0.f), IMGSZ);
    x2 = fminf(fmaxf(x2, 0.f), IMGSZ);
    y2 = fminf(fmaxf(y2, 0.f), IMGSZ);
    reinterpret_cast<float4*>(g_boxes)[j] = make_float4(x1, y1, x2, y2);
    g_valid[j] = (__fsub_rn(x2, x1) >= MINSZ) && (__fsub_rn(y2, y1) >= MINSZ);
}

/* ----------- NMS suppression mask — exact fp32, UNFUSED (match XLA) -------- */
/* Lower-triangle blocks (cb < rb) produce words the scan never reads: the     */
/* scan ORs only words w >= chunk(i). Skip them entirely.                      */
__global__ void nms_mask_kernel() {
    int rb = blockIdx.y, cb = blockIdx.x;
    if (cb < rb) return;
    int t = threadIdx.x;
    __shared__ float4 cbox[64];
    int j0 = cb * 64;
    int jg = j0 + t;
    cbox[t] = (jg < PRE) ? reinterpret_cast<const float4*>(g_boxes)[jg]
                         : make_float4(0.f, 0.f, 0.f, 0.f);
    __syncthreads();
    int i = rb * 64 + t;
    if (i >= PRE) return;
    unsigned long long bits = 0ull;
    if (j0 + 63 > i) {
        float4 b = reinterpret_cast<const float4*>(g_boxes)[i];
        float a1 = __fmul_rn(__fsub_rn(b.z, b.x), __fsub_rn(b.w, b.y));
        int jmax = min(64, PRE - j0);
        for (int jj = 0; jj < jmax; jj++) {
            int j = j0 + jj;
            if (j <= i) continue;
            float4 c = cbox[jj];
            float lx = fmaxf(b.x, c.x), ly = fmaxf(b.y, c.y);
            float rx = fminf(b.z, c.z), ry = fminf(b.w, c.w);
            float iw = fmaxf(__fsub_rn(rx, lx), 0.f);
            float ih = fmaxf(__fsub_rn(ry, ly), 0.f);
            float inter = __fmul_rn(iw, ih);
            float a2 = __fmul_rn(__fsub_rn(c.z, c.x), __fsub_rn(c.w, c.y));
            float den = fmaxf(__fsub_rn(__fadd_rn(a1, a2), inter), 1e-6f);
            float iou = __fdiv_rn(inter, den);
            if (iou > NMS_THR) bits |= (1ull << jj);
        }
    }
    g_mask[(size_t)i * MASKW + cb] = bits;
}

/* ------ greedy scan: chunked smem prefetch (256 thr) + warp-0 serial ------- */
#define CHUNK 64
__global__ void nms_scan_kernel(float* __restrict__ out) {
    extern __shared__ unsigned long long sm2[];
    unsigned long long (*rows)[MASKW] =
        reinterpret_cast<unsigned long long (*)[MASKW]>(sm2);
    volatile unsigned long long* rem = sm2 + CHUNK * MASKW;  /* 94 words */
    __shared__ int s_nkept;
    int tid = threadIdx.x;
    for (int i = tid; i < POST * 4; i += 256) out[i] = 0.f;
    for (int w = tid; w < MASKW; w += 256) {
        unsigned long long m = 0ull;
        int base = w * 64;
        for (int k = 0; k < 64; k++) {
            int j = base + k;
            if (j >= PRE || !g_valid[j]) m |= (1ull << k);
        }
        rem[w] = m;
    }
    if (tid == 0) s_nkept = 0;
    __syncthreads();

    for (int c = 0; c < MASKW; c++) {
        int base_i = c * CHUNK;
        /* prefetch 64 mask rows (words >= c only are needed; load all for simplicity) */
        for (int idx = tid; idx < CHUNK * MASKW; idx += 256) {
            int rr = idx / MASKW, col = idx - rr * MASKW;
            int gi = base_i + rr;
            rows[rr][col] = (gi < PRE && col >= c) ? g_mask[(size_t)gi * MASKW + col] : 0ull;
        }
        __syncthreads();
        if (tid < 32) {
            int lane = tid;
            int nk = s_nkept;
            for (int bit = 0; bit < CHUNK; bit++) {
                int i = base_i + bit;
                if (i >= PRE || nk >= POST) break;
                if (!((rem[c] >> bit) & 1ull)) {
                    if (lane < 4) out[nk * 4 + lane] = g_boxes[i * 4 + lane];
                    nk++;
                    for (int w = c + lane; w < MASKW; w += 32)
                        rem[w] = rem[w] | rows[bit][w];
                    __syncwarp();
                }
            }
            if (lane == 0) s_nkept = nk;
        }
        __syncthreads();
        if (s_nkept >= POST) break;
        __syncthreads();
    }
}

/* --------------------------------- launch ---------------------------------- */
extern "C" void kernel_launch(void* const* d_in, const int* in_sizes, int n_in,
                              void* d_out, int out_size) {
    (void)in_sizes; (void)n_in; (void)out_size;
    const float* feature = (const float*)d_in[0];
    const float* anchors = (const float*)d_in[1];
    const float* w_conv  = (const float*)d_in[2];
    const float* b_conv  = (const float*)d_in[3];
    const float* w_obj   = (const float*)d_in[4];
    const float* b_obj   = (const float*)d_in[5];
    const float* w_reg   = (const float*)d_in[6];
    const float* b_reg   = (const float*)d_in[7];
    float* out = (float*)d_out;

    cudaFuncSetAttribute(sort_kernel, cudaFuncAttributeMaxDynamicSharedMemorySize, 65536);
    cudaFuncSetAttribute(nms_scan_kernel, cudaFuncAttributeMaxDynamicSharedMemorySize, 65536);

    zero_kernel<<<256, 256>>>();
    transpose_w_kernel<<<(KTOT * 256 + 255) / 256, 256>>>(w_conv);
    conv3x3_kernel<<<dim3(313, 2), 256>>>(feature, b_conv);
    heads_kernel<<<313, 128>>>(w_obj, b_obj, w_reg, b_reg);
    select_kernel<<<1, 1024>>>(0);
    hist2_kernel<<<1407, 256>>>();
    select_kernel<<<1, 1024>>>(1);
    compact_kernel<<<1407, 256>>>();
    finalize_kernel<<<1, 1024>>>();
    sort_kernel<<<1, 1024, 65536>>>();
    decode_kernel<<<24, 256>>>(anchors);
    nms_mask_kernel<<<dim3(94, 94), 64>>>();
    nms_scan_kernel<<<1, 256, (CHUNK * MASKW + MASKW) * 8>>>(out);
}